// round 2
// baseline (speedup 1.0000x reference)
#include <cuda_runtime.h>
#include <math.h>

#define EPSF 1e-5f
#define PAD 3
#define TW 16
#define TH 16
#define TPW 22
#define TPH 22
#define TPIX (TPW*TPH)   /* 484 */

/* shared memory layout (float offsets) */
#define SM_X     0        /* 64*484 = 30976 floats                             */
#define SM_WR    30976    /* [c][16] BN_r-folded w_reduce (transposed), 1024   */
#define SM_BR    32000    /* 16                                                */
#define SM_WS    32016    /* [g][r][52] w_span transposed+padded, 3328         */
#define SM_BSPAN 35344    /* [g][52] padded, 208                               */
#define SM_SI    35552    /* 64 BN_i scale                                     */
#define SM_SHI   35616    /* 64 BN_i shift                                     */
#define SM_W2    35680    /* [ob=8][oo=16][c=128] folded conv|map, 16384       */
#define SM_CST   52064    /* 128 combined output bias                          */
#define SM_FLOATS 52192
#define SMEM_BYTES (SM_FLOATS*4)   /* 208768 B */

typedef unsigned long long u64;

__device__ __forceinline__ u64 pk2(float a, float b) {
    u64 r;
    asm("mov.b64 %0, {%1, %2};" : "=l"(r) : "r"(__float_as_uint(a)), "r"(__float_as_uint(b)));
    return r;
}
__device__ __forceinline__ u64 ffma2(u64 a, u64 b, u64 c) {
    u64 d;
    asm("fma.rn.f32x2 %0, %1, %2, %3;" : "=l"(d) : "l"(a), "l"(b), "l"(c));
    return d;
}
__device__ __forceinline__ void upk2(u64 v, float& lo, float& hi) {
    unsigned int l, h;
    asm("mov.b64 {%0, %1}, %2;" : "=r"(l), "=r"(h) : "l"(v));
    lo = __uint_as_float(l); hi = __uint_as_float(h);
}
__device__ __forceinline__ float gelu_f(float v) {
    return 0.5f * v * (1.0f + erff(v * 0.70710678118654752f));
}

__global__ void __launch_bounds__(256, 1)
bneck_kernel(const float* __restrict__ x,
             const float* __restrict__ w_reduce,
             const float* __restrict__ g_r, const float* __restrict__ b_r,
             const float* __restrict__ m_r, const float* __restrict__ v_r,
             const float* __restrict__ w_span, const float* __restrict__ b_span,
             const float* __restrict__ g_i, const float* __restrict__ b_i,
             const float* __restrict__ m_i, const float* __restrict__ v_i,
             const float* __restrict__ w_conv,
             const float* __restrict__ g_c, const float* __restrict__ b_c,
             const float* __restrict__ m_c, const float* __restrict__ v_c,
             const float* __restrict__ w_map, const float* __restrict__ b_map,
             const float* __restrict__ g_m, const float* __restrict__ b_m,
             const float* __restrict__ m_m, const float* __restrict__ v_m,
             float* __restrict__ out)
{
    extern __shared__ float sm[];
    const int tid = threadIdx.x;
    const int bb  = blockIdx.z;
    const int h0  = blockIdx.y * TH;
    const int w0  = blockIdx.x * TW;

    /* ---------- load padded x tile ---------- */
    {
        const int xbase = bb * 64 * 9216;
        for (int i = tid; i < 64 * TPIX; i += 256) {
            int c  = i / TPIX;
            int p  = i - c * TPIX;
            int r  = p / TPW;
            int cl = p - r * TPW;
            int gh = h0 + r - PAD;
            int gw = w0 + cl - PAD;
            float v = 0.f;
            if ((unsigned)gh < 96u && (unsigned)gw < 96u)
                v = x[xbase + c * 9216 + gh * 96 + gw];
            sm[SM_X + i] = v;
        }
    }

    /* ---------- fold BN into weights ---------- */
    for (int i = tid; i < 16 * 64; i += 256) {       /* WR[c][r] */
        int c = i >> 4, r = i & 15;
        float sc = g_r[r] * rsqrtf(v_r[r] + EPSF);
        sm[SM_WR + c * 16 + r] = w_reduce[r * 64 + c] * sc;
    }
    if (tid < 16) {
        float sc = g_r[tid] * rsqrtf(v_r[tid] + EPSF);
        sm[SM_BR + tid] = b_r[tid] - m_r[tid] * sc;
    }
    for (int i = tid; i < 4 * 16 * 52; i += 256) {   /* WS[g][r][52] padded */
        int g = i / 832, rem = i - g * 832;
        int r = rem / 52, kk = rem - r * 52;
        float v = (kk < 49) ? w_span[(g * 49 + kk) * 16 + r] : 0.f;
        sm[SM_WS + i] = v;
    }
    if (tid < 4 * 52) {                               /* BSPAN[g][52] padded */
        int g = tid / 52, kk = tid - g * 52;
        sm[SM_BSPAN + tid] = (kk < 49) ? b_span[g * 49 + kk] : 0.f;
    }
    if (tid < 64) {
        float sc = g_i[tid] * rsqrtf(v_i[tid] + EPSF);
        sm[SM_SI + tid]  = sc;
        sm[SM_SHI + tid] = b_i[tid] - m_i[tid] * sc;
    }
    for (int i = tid; i < 128 * 128; i += 256) {      /* W2[ob][oo][128] */
        int ob = i >> 11, oo = (i >> 7) & 15, c = i & 127;
        int o = ob * 16 + oo;
        float v;
        if (c < 64) v = w_conv[o * 64 + c]        * (g_c[o] * rsqrtf(v_c[o] + EPSF));
        else        v = w_map [o * 64 + (c - 64)] * (g_m[o] * rsqrtf(v_m[o] + EPSF));
        sm[SM_W2 + i] = v;
    }
    if (tid < 128) {
        float sc_c = g_c[tid] * rsqrtf(v_c[tid] + EPSF);
        float sc_m = g_m[tid] * rsqrtf(v_m[tid] + EPSF);
        sm[SM_CST + tid] = (b_c[tid] - m_c[tid] * sc_c)
                         + sc_m * b_map[tid]
                         + (b_m[tid] - m_m[tid] * sc_m);
    }
    __syncthreads();

    /* ---------- per-pixel compute ---------- */
    const int px = tid & 15;
    const int py = tid >> 4;
    const int cen = (py + PAD) * TPW + (px + PAD);

    /* reduce: t = relu(WR^T xc + br), packed f32x2, 8 parallel chains */
    u64 t2[8];
    {
        const u64* br2 = (const u64*)(sm + SM_BR);
#pragma unroll
        for (int q = 0; q < 8; q++) t2[q] = br2[q];
    }
#pragma unroll
    for (int c = 0; c < 64; c++) {
        float xv = sm[SM_X + c * TPIX + cen];
        u64 xv2 = pk2(xv, xv);
        const ulonglong2* w2 = (const ulonglong2*)(sm + SM_WR + c * 16);
#pragma unroll
        for (int q = 0; q < 4; q++) {
            ulonglong2 w = w2[q];
            t2[2 * q + 0] = ffma2(w.x, xv2, t2[2 * q + 0]);
            t2[2 * q + 1] = ffma2(w.y, xv2, t2[2 * q + 1]);
        }
    }
    float t[16];
#pragma unroll
    for (int q = 0; q < 8; q++) {
        float lo, hi; upk2(t2[q], lo, hi);
        t[2 * q] = fmaxf(lo, 0.f); t[2 * q + 1] = fmaxf(hi, 0.f);
    }

    /* span (packed, vectorized loads) + involution (7-way ILP) + BN + gelu */
    float x1[64];
#pragma unroll 1
    for (int g = 0; g < 4; g++) {
        u64 kq[26];
        {
            const u64* b2 = (const u64*)(sm + SM_BSPAN + g * 52);
#pragma unroll
            for (int q = 0; q < 26; q++) kq[q] = b2[q];
        }
#pragma unroll
        for (int r = 0; r < 16; r++) {
            u64 tv2 = pk2(t[r], t[r]);
            const ulonglong2* wsr = (const ulonglong2*)(sm + SM_WS + g * 832 + r * 52);
#pragma unroll
            for (int q = 0; q < 13; q++) {
                ulonglong2 w = wsr[q];
                kq[2 * q + 0] = ffma2(w.x, tv2, kq[2 * q + 0]);
                kq[2 * q + 1] = ffma2(w.y, tv2, kq[2 * q + 1]);
            }
        }
        float kk[52];
#pragma unroll
        for (int q = 0; q < 26; q++) upk2(kq[q], kk[2 * q], kk[2 * q + 1]);

#pragma unroll
        for (int ci = 0; ci < 16; ci++) {
            int c = g * 16 + ci;
            const float* xb = sm + SM_X + c * TPIX + py * TPW + px;
            float a[7];
#pragma unroll
            for (int i = 0; i < 7; i++) {
                float ai = kk[i * 7] * xb[i * TPW];
#pragma unroll
                for (int j = 1; j < 7; j++)
                    ai = fmaf(kk[i * 7 + j], xb[i * TPW + j], ai);
                a[i] = ai;
            }
            float acc = ((a[0] + a[1]) + (a[2] + a[3])) + ((a[4] + a[5]) + a[6]);
            float v = fmaf(acc, sm[SM_SI + c], sm[SM_SHI + c]);
            x1[c] = gelu_f(v);
        }
    }

    /* pack GEMV input vector: yv[0:32)=x1 pairs, yv[32:64)=x center pairs */
    u64 yv[64];
#pragma unroll
    for (int q = 0; q < 32; q++) yv[q] = pk2(x1[2 * q], x1[2 * q + 1]);
#pragma unroll
    for (int q = 0; q < 32; q++) {
        float lo = sm[SM_X + (2 * q)     * TPIX + cen];
        float hi = sm[SM_X + (2 * q + 1) * TPIX + cen];
        yv[32 + q] = pk2(lo, hi);
    }

    /* fused 128x128 GEMV: LDS.128 broadcast weights + f32x2 FMA */
    const int obase = bb * 128 * 9216 + (h0 + py) * 96 + (w0 + px);
#pragma unroll 1
    for (int ob = 0; ob < 8; ob++) {
        u64 acc[16];
#pragma unroll
        for (int oo = 0; oo < 16; oo++) acc[oo] = 0ULL;
        const ulonglong2* wq = (const ulonglong2*)(sm + SM_W2 + ob * 16 * 128);
#pragma unroll 2
        for (int cq = 0; cq < 32; cq++) {          /* 4 channels per step */
            u64 ya = yv[2 * cq], yb = yv[2 * cq + 1];
#pragma unroll
            for (int oo = 0; oo < 16; oo++) {
                ulonglong2 w = wq[oo * 32 + cq];
                acc[oo] = ffma2(w.x, ya, acc[oo]);
                acc[oo] = ffma2(w.y, yb, acc[oo]);
            }
        }
#pragma unroll
        for (int oo = 0; oo < 16; oo++) {
            float lo, hi; upk2(acc[oo], lo, hi);
            float s = lo + hi + sm[SM_CST + ob * 16 + oo];
            out[obase + (ob * 16 + oo) * 9216] = gelu_f(s);
        }
    }
}

extern "C" void kernel_launch(void* const* d_in, const int* in_sizes, int n_in,
                              void* d_out, int out_size)
{
    (void)in_sizes; (void)n_in; (void)out_size;
    const float* x        = (const float*)d_in[0];
    const float* w_reduce = (const float*)d_in[1];
    const float* g_r = (const float*)d_in[2];
    const float* b_r = (const float*)d_in[3];
    const float* m_r = (const float*)d_in[4];
    const float* v_r = (const float*)d_in[5];
    const float* w_span = (const float*)d_in[6];
    const float* b_span = (const float*)d_in[7];
    const float* g_i = (const float*)d_in[8];
    const float* b_i = (const float*)d_in[9];
    const float* m_i = (const float*)d_in[10];
    const float* v_i = (const float*)d_in[11];
    const float* w_conv = (const float*)d_in[12];
    const float* g_c = (const float*)d_in[13];
    const float* b_c = (const float*)d_in[14];
    const float* m_c = (const float*)d_in[15];
    const float* v_c = (const float*)d_in[16];
    const float* w_map = (const float*)d_in[17];
    const float* b_map = (const float*)d_in[18];
    const float* g_m = (const float*)d_in[19];
    const float* b_m = (const float*)d_in[20];
    const float* m_m = (const float*)d_in[21];
    const float* v_m = (const float*)d_in[22];
    float* out = (float*)d_out;

    cudaFuncSetAttribute(bneck_kernel, cudaFuncAttributeMaxDynamicSharedMemorySize, SMEM_BYTES);

    dim3 grid(96 / TW, 96 / TH, 4);   /* 6 x 6 x 4 = 144 blocks */
    dim3 block(256);
    bneck_kernel<<<grid, block, SMEM_BYTES>>>(
        x, w_reduce, g_r, b_r, m_r, v_r, w_span, b_span,
        g_i, b_i, m_i, v_i, w_conv, g_c, b_c, m_c, v_c,
        w_map, b_map, g_m, b_m, m_m, v_m, out);
}